// round 15
// baseline (speedup 1.0000x reference)
#include <cuda_runtime.h>
#include <cuda_bf16.h>
#include <cstdint>
#include <math.h>

// Problem constants
#define BATCH 16
#define DIMC  512
#define NPTS  4096

// ---------------------------------------------------------------------------
// Scratch: bf16 split pairs (hi = rn(v), lo = rn(v - hi)), plain K-major.
// ---------------------------------------------------------------------------
__device__ __nv_bfloat16 g_xh [BATCH * DIMC * NPTS];
__device__ __nv_bfloat16 g_xl [BATCH * DIMC * NPTS];
__device__ __nv_bfloat16 g_xTh[BATCH * NPTS * DIMC];
__device__ __nv_bfloat16 g_xTl[BATCH * NPTS * DIMC];
__device__ __nv_bfloat16 g_Wqh[DIMC * DIMC];
__device__ __nv_bfloat16 g_Wql[DIMC * DIMC];
__device__ __nv_bfloat16 g_Wkh[DIMC * DIMC];
__device__ __nv_bfloat16 g_Wkl[DIMC * DIMC];
__device__ __nv_bfloat16 g_WvTh[DIMC * DIMC];
__device__ __nv_bfloat16 g_WvTl[DIMC * DIMC];
__device__ __nv_bfloat16 g_Gh[BATCH * DIMC * DIMC];
__device__ __nv_bfloat16 g_Gl[BATCH * DIMC * DIMC];
__device__ __nv_bfloat16 g_Th[BATCH * DIMC * DIMC];
__device__ __nv_bfloat16 g_Tl[BATCH * DIMC * DIMC];
__device__ __nv_bfloat16 g_Ah[BATCH * DIMC * DIMC];
__device__ __nv_bfloat16 g_Al[BATCH * DIMC * DIMC];
__device__ __nv_bfloat16 g_Mh[BATCH * DIMC * DIMC];
__device__ __nv_bfloat16 g_Ml[BATCH * DIMC * DIMC];
__device__ float g_S[BATCH * DIMC * DIMC];           // plain logits

// Upper-triangle tile map for the symmetric G GEMM (4x4 tile grid -> 10 tiles)
__device__ __constant__ int TRI_I[10] = {0,0,0,0,1,1,1,2,2,3};
__device__ __constant__ int TRI_J[10] = {0,1,2,3,1,2,3,2,3,3};

// ===========================================================================
// Helpers
// ===========================================================================
__device__ __forceinline__ void bf16_split(float v, __nv_bfloat16& h, __nv_bfloat16& l) {
    h = __float2bfloat16_rn(v);
    l = __float2bfloat16_rn(v - __bfloat162float(h));
}
__device__ __forceinline__ uint32_t pack2(__nv_bfloat16 a, __nv_bfloat16 b) {
    uint16_t ua, ub;
    memcpy(&ua, &a, 2); memcpy(&ub, &b, 2);
    return (uint32_t)ua | ((uint32_t)ub << 16);
}

#define CP_ASYNC16(saddr, gptr) \
    asm volatile("cp.async.cg.shared.global [%0], [%1], 16;" \
        :: "r"(saddr), "l"(gptr) : "memory")
#define CP_COMMIT()  asm volatile("cp.async.commit_group;" ::: "memory")
#define CP_WAIT(n)   asm volatile("cp.async.wait_group %0;" :: "n"(n) : "memory")

__device__ __forceinline__ uint32_t smem_u32(const void* p) {
    uint32_t a;
    asm("{ .reg .u64 t; cvta.to.shared.u64 t, %1; cvt.u32.u64 %0, t; }"
        : "=r"(a) : "l"(p));
    return a;
}

__device__ __forceinline__ void mma_bf16(
    float c[4], uint32_t a0, uint32_t a1, uint32_t a2, uint32_t a3,
    uint32_t b0, uint32_t b1)
{
    asm("mma.sync.aligned.m16n8k16.row.col.f32.bf16.bf16.f32 "
        "{%0,%1,%2,%3}, {%4,%5,%6,%7}, {%8,%9}, {%0,%1,%2,%3};"
        : "+f"(c[0]), "+f"(c[1]), "+f"(c[2]), "+f"(c[3])
        : "r"(a0), "r"(a1), "r"(a2), "r"(a3), "r"(b0), "r"(b1));
}

#define LDSM_X4(r0, r1, r2, r3, addr) \
    asm("ldmatrix.sync.aligned.m8n8.x4.shared.b16 {%0,%1,%2,%3}, [%4];" \
        : "=r"(r0), "=r"(r1), "=r"(r2), "=r"(r3) : "r"(addr))

// ===========================================================================
// bf16x2-split NT GEMM:  C[m][n] = alpha * sum_k A[m][k]*B[n][k]
//   A = Ah+Al, B = Bh+Bl (bf16); acc += Al*Bh + Ah*Bh + Ah*Bl.
// CTA tile 128x128, BK=32 (2 x k16 HMMA). 512 threads, 16 warps 4(m)x4(n),
// warp tile 32x32. 3-STAGE cp.async pipeline (CP_WAIT(1): the consumed group
// was issued two iterations earlier -> barrier never waits on a fresh load),
// 2 CTAs/SM. SMEM row layout = [hi 64B | lo 64B], pitch 144B (rows bank-shift
// 4 mod 32 -> LDSM conflict-free); gmem layout unchanged (4 arrays).
// symTri != 0: blockIdx.x indexes TRI_I/TRI_J; off-diagonal tiles mirror-write
//   the transposed tile (C symmetric, A==B); mirrored bytes bit-identical.
// ===========================================================================
#define BM 128
#define BN 128
#define PITCHB 144                          // bytes per combined hi|lo row
#define ATILE_BYTES (128 * PITCHB)          // 18432 per operand (A or B)
#define STAGE_BYTES (2 * ATILE_BYTES)       // A + B = 36864
#define NSTAGE 3
#define SMEM_BYTES (NSTAGE * STAGE_BYTES)   // 110592
#define GTHREADS 512

__global__ __launch_bounds__(GTHREADS, 2) void gemm_bf16x2_nt(
    const __nv_bfloat16* __restrict__ Ah, const __nv_bfloat16* __restrict__ Al,
    const __nv_bfloat16* __restrict__ Bh, const __nv_bfloat16* __restrict__ Bl,
    float* __restrict__ Cp, __nv_bfloat16* __restrict__ Ch, __nv_bfloat16* __restrict__ Cl,
    int K, int lda, int ldb, int ldc, int ldcp,
    long long sA, long long sB, long long sC, long long sCp, float alpha,
    int symTri)
{
    extern __shared__ char smem[];
    const int tid  = threadIdx.x;
    const int wid  = tid >> 5;
    const int lane = tid & 31;
    const int wm   = wid & 3;      // 4 m-groups x 32 rows
    const int wn   = wid >> 2;     // 4 n-groups x 32 cols

    int bx = blockIdx.x, by = blockIdx.y;
    if (symTri) { by = TRI_I[blockIdx.x]; bx = TRI_J[blockIdx.x]; }

    const long long offA = blockIdx.z * sA + (long long)(by * BM) * lda;
    const long long offB = blockIdx.z * sB + (long long)(bx * BN) * ldb;
    Ah += offA; Al += offA;
    Bh += offB; Bl += offB;

    const uint32_t smem_base = smem_u32(smem);

    float acc[2][4][4];
#pragma unroll
    for (int i = 0; i < 2; i++)
#pragma unroll
        for (int j = 0; j < 4; j++)
#pragma unroll
            for (int r = 0; r < 4; r++) acc[i][j][r] = 0.0f;

    const int ktiles = K / 32;

    // Loader: 512 threads; row = tid>>2, quarter q = tid&3.
    // Each thread: one 16B chunk from each of Ah, Al, Bh, Bl.
    const int l_row = tid >> 2;
    const int l_q   = tid & 3;
    const long long gA = (long long)l_row * lda + l_q * 8;
    const long long gB = (long long)l_row * ldb + l_q * 8;
    const uint32_t  sRow = (uint32_t)(l_row * PITCHB + l_q * 16);
    auto issue_tile = [&](int kt, int st) {
        const uint32_t s0 = smem_base + (uint32_t)(st * STAGE_BYTES);
        const int ko = kt * 32;
        CP_ASYNC16(s0 + sRow,                    Ah + gA + ko);
        CP_ASYNC16(s0 + sRow + 64,               Al + gA + ko);
        CP_ASYNC16(s0 + ATILE_BYTES + sRow,      Bh + gB + ko);
        CP_ASYNC16(s0 + ATILE_BYTES + sRow + 64, Bl + gB + ko);
        CP_COMMIT();
    };

    issue_tile(0, 0);
    if (ktiles > 1) issue_tile(1, 1);

    const int gid = lane >> 2;
    const int tig = lane & 3;

    // ldmatrix lane-address offsets (within the hi half; lo = +64).
    const int lm = lane >> 3;   // matrix index 0..3
    const int lr = lane & 7;
    const uint32_t laneA = (uint32_t)(((lm & 1) * 8 + lr) * PITCHB + (lm >> 1) * 16);
    const uint32_t laneB = (uint32_t)((((lm & 2) ? 8 : 0) + lr) * PITCHB + (lm & 1) * 16);

    const uint32_t warpA = (uint32_t)(wm * 32 * PITCHB) + laneA;
    const uint32_t warpB = (uint32_t)(wn * 32 * PITCHB) + laneB;

    for (int kt = 0; kt < ktiles; ++kt) {
        const int st = kt % NSTAGE;
        if (kt + 1 < ktiles) { CP_WAIT(1); } else { CP_WAIT(0); }
        __syncthreads();   // all warps done with stage (kt-1)%3; reuse is safe
        if (kt + 2 < ktiles) issue_tile(kt + 2, (kt + 2) % NSTAGE);

        const uint32_t sA0 = smem_base + st * STAGE_BYTES;
        const uint32_t sB0 = sA0 + ATILE_BYTES;

#pragma unroll
        for (int s = 0; s < 2; ++s) {          // 2 x k16 steps
            const uint32_t ks = s * 32;
            uint32_t a[2][4], b[4][2];

            // ---- term 1: Al * Bh
            {
                const uint32_t aB = sA0 + warpA + 64 + ks;   // lo half
                LDSM_X4(a[0][0], a[0][1], a[0][2], a[0][3], aB);
                LDSM_X4(a[1][0], a[1][1], a[1][2], a[1][3], aB + 16 * PITCHB);
                const uint32_t bB = sB0 + warpB + ks;        // hi half
                LDSM_X4(b[0][0], b[0][1], b[1][0], b[1][1], bB);
                LDSM_X4(b[2][0], b[2][1], b[3][0], b[3][1], bB + 16 * PITCHB);
            }
#pragma unroll
            for (int fi = 0; fi < 2; ++fi)
#pragma unroll
                for (int fj = 0; fj < 4; ++fj)
                    mma_bf16(acc[fi][fj], a[fi][0], a[fi][1], a[fi][2], a[fi][3],
                             b[fj][0], b[fj][1]);

            // ---- term 2: Ah * Bh  (Bh resident; reload a = Ah)
            {
                const uint32_t aB = sA0 + warpA + ks;        // hi half
                LDSM_X4(a[0][0], a[0][1], a[0][2], a[0][3], aB);
                LDSM_X4(a[1][0], a[1][1], a[1][2], a[1][3], aB + 16 * PITCHB);
            }
#pragma unroll
            for (int fi = 0; fi < 2; ++fi)
#pragma unroll
                for (int fj = 0; fj < 4; ++fj)
                    mma_bf16(acc[fi][fj], a[fi][0], a[fi][1], a[fi][2], a[fi][3],
                             b[fj][0], b[fj][1]);

            // ---- term 3: Ah * Bl  (Ah resident; reload b = Bl)
            {
                const uint32_t bB = sB0 + warpB + 64 + ks;   // lo half
                LDSM_X4(b[0][0], b[0][1], b[1][0], b[1][1], bB);
                LDSM_X4(b[2][0], b[2][1], b[3][0], b[3][1], bB + 16 * PITCHB);
            }
#pragma unroll
            for (int fi = 0; fi < 2; ++fi)
#pragma unroll
                for (int fj = 0; fj < 4; ++fj)
                    mma_bf16(acc[fi][fj], a[fi][0], a[fi][1], a[fi][2], a[fi][3],
                             b[fj][0], b[fj][1]);
        }
    }

    // Epilogue
    const bool mirror = symTri && (bx != by);
    const int crow0 = by * BM + wm * 32 + gid;
    const int ccol0 = bx * BN + wn * 32 + 2 * tig;
#pragma unroll
    for (int fi = 0; fi < 2; ++fi) {
#pragma unroll
        for (int fj = 0; fj < 4; ++fj) {
            const int r0 = crow0 + fi * 16;
            const int c0 = ccol0 + fj * 8;
            const float v0 = acc[fi][fj][0] * alpha;
            const float v1 = acc[fi][fj][1] * alpha;
            const float v2 = acc[fi][fj][2] * alpha;
            const float v3 = acc[fi][fj][3] * alpha;
            if (Cp) {
                const long long e0 = blockIdx.z * sC + (long long)r0 * ldc + c0;
                *(float2*)(Cp + e0)           = make_float2(v0, v1);
                *(float2*)(Cp + e0 + 8 * ldc) = make_float2(v2, v3);
            }
            if (Ch) {
                const long long e0 = blockIdx.z * sCp + (long long)r0 * ldcp + c0;
                const long long e1 = e0 + 8LL * ldcp;
                __nv_bfloat16 h0, l0, h1, l1, h2, l2, h3, l3;
                bf16_split(v0, h0, l0); bf16_split(v1, h1, l1);
                bf16_split(v2, h2, l2); bf16_split(v3, h3, l3);
                *(uint32_t*)(Ch + e0) = pack2(h0, h1);
                *(uint32_t*)(Cl + e0) = pack2(l0, l1);
                *(uint32_t*)(Ch + e1) = pack2(h2, h3);
                *(uint32_t*)(Cl + e1) = pack2(l2, l3);
                if (mirror) {
                    const long long mb = blockIdx.z * sCp;
                    Ch[mb + (long long)(c0    ) * ldcp + r0    ] = h0;
                    Ch[mb + (long long)(c0 + 1) * ldcp + r0    ] = h1;
                    Ch[mb + (long long)(c0    ) * ldcp + r0 + 8] = h2;
                    Ch[mb + (long long)(c0 + 1) * ldcp + r0 + 8] = h3;
                    Cl[mb + (long long)(c0    ) * ldcp + r0    ] = l0;
                    Cl[mb + (long long)(c0 + 1) * ldcp + r0    ] = l1;
                    Cl[mb + (long long)(c0    ) * ldcp + r0 + 8] = l2;
                    Cl[mb + (long long)(c0 + 1) * ldcp + r0 + 8] = l3;
                }
            }
        }
    }
}

// ===========================================================================
// Split kernel for x: 32x32 tile -> bf16 hi/lo, straight + transposed.
// ===========================================================================
__global__ __launch_bounds__(256) void split_bf16_kernel(
    const float* __restrict__ in,
    __nv_bfloat16* __restrict__ oH,  __nv_bfloat16* __restrict__ oL,
    __nv_bfloat16* __restrict__ oTH, __nv_bfloat16* __restrict__ oTL,
    int rows, int cols, long long sin, long long so, long long soT)
{
    __shared__ __nv_bfloat16 hi[32][34], lo[32][34];
    const float* I = in + (long long)blockIdx.z * sin;
    const int c0 = blockIdx.x * 32;
    const int r0 = blockIdx.y * 32;
    const int tx = threadIdx.x & 31, ty = threadIdx.x >> 5;

#pragma unroll
    for (int i = ty; i < 32; i += 8) {
        const float v = I[(long long)(r0 + i) * cols + c0 + tx];
        bf16_split(v, hi[i][tx], lo[i][tx]);
    }
    __syncthreads();

    const int i0 = threadIdx.x >> 4;
    const int cp = threadIdx.x & 15;
    if (oH) {
#pragma unroll
        for (int p = 0; p < 2; ++p) {
            const int i = i0 + p * 16;
            const long long e = (long long)blockIdx.z * so
                              + (long long)(r0 + i) * cols + c0 + 2 * cp;
            *(uint32_t*)(oH + e) = pack2(hi[i][2 * cp], hi[i][2 * cp + 1]);
            *(uint32_t*)(oL + e) = pack2(lo[i][2 * cp], lo[i][2 * cp + 1]);
        }
    }
    if (oTH) {
#pragma unroll
        for (int p = 0; p < 2; ++p) {
            const int i = i0 + p * 16;
            const long long e = (long long)blockIdx.z * soT
                              + (long long)(c0 + i) * rows + r0 + 2 * cp;
            *(uint32_t*)(oTH + e) = pack2(hi[2 * cp][i], hi[2 * cp + 1][i]);
            *(uint32_t*)(oTL + e) = pack2(lo[2 * cp][i], lo[2 * cp + 1][i]);
        }
    }
}

// ===========================================================================
// Merged weight split: blockIdx.z selects 0:Wq, 1:Wk, 2:Wv(transposed).
// ===========================================================================
__global__ __launch_bounds__(256) void split_weights_kernel(
    const float* __restrict__ Wq, const float* __restrict__ Wk,
    const float* __restrict__ Wv,
    __nv_bfloat16* __restrict__ Wqh, __nv_bfloat16* __restrict__ Wql,
    __nv_bfloat16* __restrict__ Wkh, __nv_bfloat16* __restrict__ Wkl,
    __nv_bfloat16* __restrict__ WvTh, __nv_bfloat16* __restrict__ WvTl)
{
    __shared__ __nv_bfloat16 hi[32][34], lo[32][34];
    const int which = blockIdx.z;
    const float* I = which == 0 ? Wq : which == 1 ? Wk : Wv;
    const int c0 = blockIdx.x * 32;
    const int r0 = blockIdx.y * 32;
    const int tx = threadIdx.x & 31, ty = threadIdx.x >> 5;

#pragma unroll
    for (int i = ty; i < 32; i += 8) {
        const float v = I[(long long)(r0 + i) * DIMC + c0 + tx];
        bf16_split(v, hi[i][tx], lo[i][tx]);
    }
    __syncthreads();

    const int i0 = threadIdx.x >> 4;
    const int cp = threadIdx.x & 15;
    if (which < 2) {
        __nv_bfloat16* oH = which == 0 ? Wqh : Wkh;
        __nv_bfloat16* oL = which == 0 ? Wql : Wkl;
#pragma unroll
        for (int p = 0; p < 2; ++p) {
            const int i = i0 + p * 16;
            const long long e = (long long)(r0 + i) * DIMC + c0 + 2 * cp;
            *(uint32_t*)(oH + e) = pack2(hi[i][2 * cp], hi[i][2 * cp + 1]);
            *(uint32_t*)(oL + e) = pack2(lo[i][2 * cp], lo[i][2 * cp + 1]);
        }
    } else {
#pragma unroll
        for (int p = 0; p < 2; ++p) {
            const int i = i0 + p * 16;
            const long long e = (long long)(c0 + i) * DIMC + r0 + 2 * cp;
            *(uint32_t*)(WvTh + e) = pack2(hi[2 * cp][i], hi[2 * cp + 1][i]);
            *(uint32_t*)(WvTl + e) = pack2(lo[2 * cp][i], lo[2 * cp + 1][i]);
        }
    }
}

// ===========================================================================
// Row softmax over S (fp32), writing bf16-split A = softmax(S).
// ===========================================================================
__global__ __launch_bounds__(256) void softmax_split_kernel(
    const float* __restrict__ S,
    __nv_bfloat16* __restrict__ AH, __nv_bfloat16* __restrict__ AL)
{
    __shared__ float red[8];
    const long long row = blockIdx.x;
    const float* p = S + row * DIMC;
    const int t = threadIdx.x;
    const int lane = t & 31, warp = t >> 5;

    const float v0 = p[2 * t];
    const float v1 = p[2 * t + 1];

    float m = fmaxf(v0, v1);
#pragma unroll
    for (int o = 16; o; o >>= 1) m = fmaxf(m, __shfl_xor_sync(0xFFFFFFFFu, m, o));
    if (lane == 0) red[warp] = m;
    __syncthreads();
    m = red[0];
#pragma unroll
    for (int w = 1; w < 8; ++w) m = fmaxf(m, red[w]);
    __syncthreads();

    const float e0 = expf(v0 - m);
    const float e1 = expf(v1 - m);
    float sum = e0 + e1;
#pragma unroll
    for (int o = 16; o; o >>= 1) sum += __shfl_xor_sync(0xFFFFFFFFu, sum, o);
    if (lane == 0) red[warp] = sum;
    __syncthreads();
    sum = red[0];
#pragma unroll
    for (int w = 1; w < 8; ++w) sum += red[w];
    const float inv = 1.0f / sum;

    __nv_bfloat16 h0, l0, h1, l1;
    bf16_split(e0 * inv, h0, l0);
    bf16_split(e1 * inv, h1, l1);
    *(uint32_t*)(AH + row * DIMC + 2 * t) = pack2(h0, h1);
    *(uint32_t*)(AL + row * DIMC + 2 * t) = pack2(l0, l1);
}

// ===========================================================================
// Launch chain (all GEMMs NT, bf16x2-split HMMA.16816, ldmatrix frags,
// 3-stage pipeline):
//   split x;  G = x.x^T (SYMMETRIC: 10/16 tiles + mirror);  split weights;
//   T = Wq.G; S = (1/tau) T.Wk^T; A = softmax(S); M = A.Wv; out = M.x
// ===========================================================================
extern "C" void kernel_launch(void* const* d_in, const int* in_sizes, int n_in,
                              void* d_out, int out_size)
{
    const float* x  = (const float*)d_in[0];
    const float* Wq = (const float*)d_in[1];
    const float* Wk = (const float*)d_in[2];
    const float* Wv = (const float*)d_in[3];
    float* out = (float*)d_out;

    __nv_bfloat16 *xh, *xl, *xTh, *xTl, *Wqh, *Wql, *Wkh, *Wkl, *WvTh, *WvTl;
    __nv_bfloat16 *Gh, *Gl, *Th, *Tl, *Ahp, *Alp, *Mh, *Ml;
    float* S;
    cudaGetSymbolAddress((void**)&xh,   g_xh);
    cudaGetSymbolAddress((void**)&xl,   g_xl);
    cudaGetSymbolAddress((void**)&xTh,  g_xTh);
    cudaGetSymbolAddress((void**)&xTl,  g_xTl);
    cudaGetSymbolAddress((void**)&Wqh,  g_Wqh);
    cudaGetSymbolAddress((void**)&Wql,  g_Wql);
    cudaGetSymbolAddress((void**)&Wkh,  g_Wkh);
    cudaGetSymbolAddress((void**)&Wkl,  g_Wkl);
    cudaGetSymbolAddress((void**)&WvTh, g_WvTh);
    cudaGetSymbolAddress((void**)&WvTl, g_WvTl);
    cudaGetSymbolAddress((void**)&Gh,   g_Gh);
    cudaGetSymbolAddress((void**)&Gl,   g_Gl);
    cudaGetSymbolAddress((void**)&Th,   g_Th);
    cudaGetSymbolAddress((void**)&Tl,   g_Tl);
    cudaGetSymbolAddress((void**)&Ahp,  g_Ah);
    cudaGetSymbolAddress((void**)&Alp,  g_Al);
    cudaGetSymbolAddress((void**)&Mh,   g_Mh);
    cudaGetSymbolAddress((void**)&Ml,   g_Ml);
    cudaGetSymbolAddress((void**)&S,    g_S);

    cudaFuncSetAttribute(gemm_bf16x2_nt,
                         cudaFuncAttributeMaxDynamicSharedMemorySize, SMEM_BYTES);

    const long long sX  = (long long)DIMC * NPTS;   // x / xT / out batch stride
    const long long sDD = (long long)DIMC * DIMC;
    const float inv_tau = (float)(1.0 / sqrt((double)DIMC));

    // split x (needed by G)
    {
        dim3 gx(NPTS / 32, DIMC / 32, BATCH);
        split_bf16_kernel<<<gx, 256>>>(x, xh, xl, xTh, xTl, DIMC, NPTS, sX, sX, sX);
    }

    // G[b] = x[b] . x[b]^T  -> split, SYMMETRIC: 10 upper-triangle tiles/batch
    {
        dim3 gG(10, 1, BATCH);
        gemm_bf16x2_nt<<<gG, GTHREADS, SMEM_BYTES>>>(xh, xl, xh, xl,
            nullptr, Gh, Gl,
            NPTS, NPTS, NPTS, 0, DIMC, sX, sX, 0LL, sDD, 1.0f, 1);
    }

    // split weights (one launch; needed from T onward)
    {
        dim3 gw(DIMC / 32, DIMC / 32, 3);
        split_weights_kernel<<<gw, 256>>>(Wq, Wk, Wv,
            Wqh, Wql, Wkh, Wkl, WvTh, WvTl);
    }

    dim3 gSq(DIMC / BN, DIMC / BM, BATCH);   // 4 x 4 x 16
    dim3 gOut(NPTS / BN, DIMC / BM, BATCH);  // 32 x 4 x 16

    // T[b] = Wq . G[b]  (G symmetric) -> split
    gemm_bf16x2_nt<<<gSq, GTHREADS, SMEM_BYTES>>>(Wqh, Wql, Gh, Gl,
        nullptr, Th, Tl,
        DIMC, DIMC, DIMC, 0, DIMC, 0LL, sDD, 0LL, sDD, 1.0f, 0);

    // S[b] = (1/tau) T[b] . Wk^T -> plain
    gemm_bf16x2_nt<<<gSq, GTHREADS, SMEM_BYTES>>>(Th, Tl, Wkh, Wkl,
        S, nullptr, nullptr,
        DIMC, DIMC, DIMC, DIMC, 0, sDD, 0LL, sDD, 0LL, inv_tau, 0);

    // A = softmax(S) -> split
    softmax_split_kernel<<<BATCH * DIMC, 256>>>(S, Ahp, Alp);

    // M[b] = A[b] . Wv (B = WvT) -> split
    gemm_bf16x2_nt<<<gSq, GTHREADS, SMEM_BYTES>>>(Ahp, Alp, WvTh, WvTl,
        nullptr, Mh, Ml,
        DIMC, DIMC, DIMC, 0, DIMC, sDD, 0LL, 0LL, sDD, 1.0f, 0);

    // out[b] = M[b] . x[b]  (B = xT) -> plain
    gemm_bf16x2_nt<<<gOut, GTHREADS, SMEM_BYTES>>>(Mh, Ml, xTh, xTl,
        out, nullptr, nullptr,
        DIMC, DIMC, DIMC, NPTS, 0, sDD, sX, sX, 0LL, 1.0f, 0);
}

// round 16
// speedup vs baseline: 1.7130x; 1.7130x over previous
#include <cuda_runtime.h>
#include <cuda_fp16.h>
#include <cstdint>
#include <math.h>

// Problem constants
#define BATCH 16
#define DIMC  512
#define NPTS  4096

// ---------------------------------------------------------------------------
// Scratch: fp16 split pairs (hi = rn(v), lo = rn(v - hi)), plain K-major.
// xT needs only the hi part (used solely as the 2-term out-GEMM's B operand).
// ---------------------------------------------------------------------------
__device__ __half g_xh [BATCH * DIMC * NPTS];
__device__ __half g_xl [BATCH * DIMC * NPTS];
__device__ __half g_xTh[BATCH * NPTS * DIMC];
__device__ __half g_Wqh[DIMC * DIMC];
__device__ __half g_Wql[DIMC * DIMC];
__device__ __half g_Wkh[DIMC * DIMC];
__device__ __half g_Wkl[DIMC * DIMC];
__device__ __half g_WvTh[DIMC * DIMC];
__device__ __half g_WvTl[DIMC * DIMC];
__device__ __half g_Gh[BATCH * DIMC * DIMC];
__device__ __half g_Gl[BATCH * DIMC * DIMC];
__device__ __half g_Th[BATCH * DIMC * DIMC];
__device__ __half g_Tl[BATCH * DIMC * DIMC];
__device__ __half g_Ah[BATCH * DIMC * DIMC];
__device__ __half g_Al[BATCH * DIMC * DIMC];
__device__ __half g_Mh[BATCH * DIMC * DIMC];
__device__ __half g_Ml[BATCH * DIMC * DIMC];
__device__ float g_S[BATCH * DIMC * DIMC];           // plain logits

// Upper-triangle tile map for the symmetric G GEMM (4x4 tile grid -> 10 tiles)
__device__ __constant__ int TRI_I[10] = {0,0,0,0,1,1,1,2,2,3};
__device__ __constant__ int TRI_J[10] = {0,1,2,3,1,2,3,2,3,3};

// ===========================================================================
// Helpers
// ===========================================================================
__device__ __forceinline__ void f16_split(float v, __half& h, __half& l) {
    h = __float2half_rn(v);
    l = __float2half_rn(v - __half2float(h));
}
__device__ __forceinline__ uint32_t pack2h(__half a, __half b) {
    uint16_t ua, ub;
    memcpy(&ua, &a, 2); memcpy(&ub, &b, 2);
    return (uint32_t)ua | ((uint32_t)ub << 16);
}

#define CP_ASYNC16(saddr, gptr) \
    asm volatile("cp.async.cg.shared.global [%0], [%1], 16;" \
        :: "r"(saddr), "l"(gptr) : "memory")
#define CP_COMMIT()  asm volatile("cp.async.commit_group;" ::: "memory")
#define CP_WAIT(n)   asm volatile("cp.async.wait_group %0;" :: "n"(n) : "memory")

__device__ __forceinline__ uint32_t smem_u32(const void* p) {
    uint32_t a;
    asm("{ .reg .u64 t; cvta.to.shared.u64 t, %1; cvt.u32.u64 %0, t; }"
        : "=r"(a) : "l"(p));
    return a;
}

__device__ __forceinline__ void mma_f16(
    float c[4], uint32_t a0, uint32_t a1, uint32_t a2, uint32_t a3,
    uint32_t b0, uint32_t b1)
{
    asm("mma.sync.aligned.m16n8k16.row.col.f32.f16.f16.f32 "
        "{%0,%1,%2,%3}, {%4,%5,%6,%7}, {%8,%9}, {%0,%1,%2,%3};"
        : "+f"(c[0]), "+f"(c[1]), "+f"(c[2]), "+f"(c[3])
        : "r"(a0), "r"(a1), "r"(a2), "r"(a3), "r"(b0), "r"(b1));
}

#define LDSM_X4(r0, r1, r2, r3, addr) \
    asm("ldmatrix.sync.aligned.m8n8.x4.shared.b16 {%0,%1,%2,%3}, [%4];" \
        : "=r"(r0), "=r"(r1), "=r"(r2), "=r"(r3) : "r"(addr))

// ===========================================================================
// fp16x2-split NT GEMM:  C[m][n] = alpha * sum_k A[m][k]*B[n][k]
//   A = Ah+Al, B = Bh(+Bl).  acc += Al*Bh + Ah*Bh (+ Ah*Bl if Bl != null).
// CTA tile 128x128, BK=32 (2 x k16 HMMA). 512 threads, 16 warps 4(m)x4(n),
// warp tile 32x32. 2-stage cp.async, one sync per ktile, 2 CTAs/SM.
// Fragment loads via ldmatrix.x4.  (Exact structure of the 826us R12 kernel,
// with bf16 -> fp16 and an optional 2-term mode.)
// symTri != 0: blockIdx.x indexes TRI_I/TRI_J; off-diagonal tiles mirror-write
//   the transposed tile (C symmetric, A==B); mirrored bytes bit-identical.
// ===========================================================================
#define BM 128
#define BN 128
#define PITCHB 80                          // bytes per 32-element fp16 row
#define TILE_BYTES (128 * PITCHB)          // 10240 per operand array
#define STAGE_BYTES (4 * TILE_BYTES)       // Ah, Al, Bh, Bl = 40960
#define SMEM_BYTES (2 * STAGE_BYTES)       // 81920
#define GTHREADS 512

__global__ __launch_bounds__(GTHREADS, 2) void gemm_f16x2_nt(
    const __half* __restrict__ Ah, const __half* __restrict__ Al,
    const __half* __restrict__ Bh, const __half* __restrict__ Bl,
    float* __restrict__ Cp, __half* __restrict__ Ch, __half* __restrict__ Cl,
    int K, int lda, int ldb, int ldc, int ldcp,
    long long sA, long long sB, long long sC, long long sCp, float alpha,
    int symTri)
{
    extern __shared__ char smem[];
    const int tid  = threadIdx.x;
    const int wid  = tid >> 5;
    const int lane = tid & 31;
    const int wm   = wid & 3;      // 4 m-groups x 32 rows
    const int wn   = wid >> 2;     // 4 n-groups x 32 cols
    const bool hasBl = (Bl != nullptr);

    int bx = blockIdx.x, by = blockIdx.y;
    if (symTri) { by = TRI_I[blockIdx.x]; bx = TRI_J[blockIdx.x]; }

    const long long offA = blockIdx.z * sA + (long long)(by * BM) * lda;
    const long long offB = blockIdx.z * sB + (long long)(bx * BN) * ldb;
    Ah += offA; Al += offA;
    Bh += offB; if (hasBl) Bl += offB;

    const uint32_t smem_base = smem_u32(smem);

    float acc[2][4][4];
#pragma unroll
    for (int i = 0; i < 2; i++)
#pragma unroll
        for (int j = 0; j < 4; j++)
#pragma unroll
            for (int r = 0; r < 4; r++) acc[i][j][r] = 0.0f;

    const int ktiles = K / 32;

    // Loader: 512 threads, 1 chunk per array per thread.
    const int l_row = tid >> 2;
    const int l_ch  = tid & 3;
    const long long gA = (long long)l_row * lda + l_ch * 8;
    const long long gB = (long long)l_row * ldb + l_ch * 8;
    const uint32_t  sO = (uint32_t)(l_row * PITCHB + l_ch * 16);
    auto issue_tile = [&](int kt, int st) {
        const uint32_t s0 = smem_base + (uint32_t)(st * STAGE_BYTES) + sO;
        const int ko = kt * 32;
        CP_ASYNC16(s0,                  Ah + gA + ko);
        CP_ASYNC16(s0 + TILE_BYTES,     Al + gA + ko);
        CP_ASYNC16(s0 + 2 * TILE_BYTES, Bh + gB + ko);
        if (hasBl) CP_ASYNC16(s0 + 3 * TILE_BYTES, Bl + gB + ko);
        CP_COMMIT();
    };

    issue_tile(0, 0);

    const int gid = lane >> 2;
    const int tig = lane & 3;

    // ldmatrix lane-address offsets (identical mapping to the R12 kernel).
    const int lm = lane >> 3;   // matrix index 0..3
    const int lr = lane & 7;
    const uint32_t laneA = (uint32_t)(((lm & 1) * 8 + lr) * PITCHB + (lm >> 1) * 16);
    const uint32_t laneB = (uint32_t)((((lm & 2) ? 8 : 0) + lr) * PITCHB + (lm & 1) * 16);

    const uint32_t warpA = (uint32_t)(wm * 32 * PITCHB) + laneA;
    const uint32_t warpB = (uint32_t)(wn * 32 * PITCHB) + laneB;

    for (int kt = 0; kt < ktiles; ++kt) {
        const int st = kt & 1;
        CP_WAIT(0);
        __syncthreads();   // data for kt visible; other buffer free for kt+1
        if (kt + 1 < ktiles) issue_tile(kt + 1, st ^ 1);

        const uint32_t sAh = smem_base + st * STAGE_BYTES;
        const uint32_t sAl = sAh + TILE_BYTES;
        const uint32_t sBh = sAl + TILE_BYTES;
        const uint32_t sBl = sBh + TILE_BYTES;

#pragma unroll
        for (int s = 0; s < 2; ++s) {          // 2 x k16 steps
            const uint32_t ks = s * 32;
            uint32_t a[2][4], b[4][2];

            // ---- term 1: Al * Bh
            {
                const uint32_t aB = sAl + warpA + ks;
                LDSM_X4(a[0][0], a[0][1], a[0][2], a[0][3], aB);
                LDSM_X4(a[1][0], a[1][1], a[1][2], a[1][3], aB + 16 * PITCHB);
                const uint32_t bB = sBh + warpB + ks;
                LDSM_X4(b[0][0], b[0][1], b[1][0], b[1][1], bB);
                LDSM_X4(b[2][0], b[2][1], b[3][0], b[3][1], bB + 16 * PITCHB);
            }
#pragma unroll
            for (int fi = 0; fi < 2; ++fi)
#pragma unroll
                for (int fj = 0; fj < 4; ++fj)
                    mma_f16(acc[fi][fj], a[fi][0], a[fi][1], a[fi][2], a[fi][3],
                            b[fj][0], b[fj][1]);

            // ---- term 2: Ah * Bh  (Bh resident; reload a = Ah)
            {
                const uint32_t aB = sAh + warpA + ks;
                LDSM_X4(a[0][0], a[0][1], a[0][2], a[0][3], aB);
                LDSM_X4(a[1][0], a[1][1], a[1][2], a[1][3], aB + 16 * PITCHB);
            }
#pragma unroll
            for (int fi = 0; fi < 2; ++fi)
#pragma unroll
                for (int fj = 0; fj < 4; ++fj)
                    mma_f16(acc[fi][fj], a[fi][0], a[fi][1], a[fi][2], a[fi][3],
                            b[fj][0], b[fj][1]);

            // ---- term 3: Ah * Bl  (Ah resident; reload b = Bl) — optional
            if (hasBl) {
                const uint32_t bB = sBl + warpB + ks;
                LDSM_X4(b[0][0], b[0][1], b[1][0], b[1][1], bB);
                LDSM_X4(b[2][0], b[2][1], b[3][0], b[3][1], bB + 16 * PITCHB);
#pragma unroll
                for (int fi = 0; fi < 2; ++fi)
#pragma unroll
                    for (int fj = 0; fj < 4; ++fj)
                        mma_f16(acc[fi][fj], a[fi][0], a[fi][1], a[fi][2], a[fi][3],
                                b[fj][0], b[fj][1]);
            }
        }
    }

    // Epilogue
    const bool mirror = symTri && (bx != by);
    const int crow0 = by * BM + wm * 32 + gid;
    const int ccol0 = bx * BN + wn * 32 + 2 * tig;
#pragma unroll
    for (int fi = 0; fi < 2; ++fi) {
#pragma unroll
        for (int fj = 0; fj < 4; ++fj) {
            const int r0 = crow0 + fi * 16;
            const int c0 = ccol0 + fj * 8;
            const float v0 = acc[fi][fj][0] * alpha;
            const float v1 = acc[fi][fj][1] * alpha;
            const float v2 = acc[fi][fj][2] * alpha;
            const float v3 = acc[fi][fj][3] * alpha;
            if (Cp) {
                const long long e0 = blockIdx.z * sC + (long long)r0 * ldc + c0;
                *(float2*)(Cp + e0)           = make_float2(v0, v1);
                *(float2*)(Cp + e0 + 8 * ldc) = make_float2(v2, v3);
            }
            if (Ch) {
                const long long e0 = blockIdx.z * sCp + (long long)r0 * ldcp + c0;
                const long long e1 = e0 + 8LL * ldcp;
                __half h0, l0, h1, l1, h2, l2, h3, l3;
                f16_split(v0, h0, l0); f16_split(v1, h1, l1);
                f16_split(v2, h2, l2); f16_split(v3, h3, l3);
                *(uint32_t*)(Ch + e0) = pack2h(h0, h1);
                *(uint32_t*)(Cl + e0) = pack2h(l0, l1);
                *(uint32_t*)(Ch + e1) = pack2h(h2, h3);
                *(uint32_t*)(Cl + e1) = pack2h(l2, l3);
                if (mirror) {
                    const long long mb = blockIdx.z * sCp;
                    Ch[mb + (long long)(c0    ) * ldcp + r0    ] = h0;
                    Ch[mb + (long long)(c0 + 1) * ldcp + r0    ] = h1;
                    Ch[mb + (long long)(c0    ) * ldcp + r0 + 8] = h2;
                    Ch[mb + (long long)(c0 + 1) * ldcp + r0 + 8] = h3;
                    Cl[mb + (long long)(c0    ) * ldcp + r0    ] = l0;
                    Cl[mb + (long long)(c0 + 1) * ldcp + r0    ] = l1;
                    Cl[mb + (long long)(c0    ) * ldcp + r0 + 8] = l2;
                    Cl[mb + (long long)(c0 + 1) * ldcp + r0 + 8] = l3;
                }
            }
        }
    }
}

// ===========================================================================
// Split kernel for x: 32x32 tile -> fp16 hi/lo straight, hi-only transposed.
// ===========================================================================
__global__ __launch_bounds__(256) void split_f16_kernel(
    const float* __restrict__ in,
    __half* __restrict__ oH,  __half* __restrict__ oL,
    __half* __restrict__ oTH,
    int rows, int cols, long long sin, long long so, long long soT)
{
    __shared__ __half hi[32][34], lo[32][34];
    const float* I = in + (long long)blockIdx.z * sin;
    const int c0 = blockIdx.x * 32;
    const int r0 = blockIdx.y * 32;
    const int tx = threadIdx.x & 31, ty = threadIdx.x >> 5;

#pragma unroll
    for (int i = ty; i < 32; i += 8) {
        const float v = I[(long long)(r0 + i) * cols + c0 + tx];
        f16_split(v, hi[i][tx], lo[i][tx]);
    }
    __syncthreads();

    const int i0 = threadIdx.x >> 4;
    const int cp = threadIdx.x & 15;
    if (oH) {
#pragma unroll
        for (int p = 0; p < 2; ++p) {
            const int i = i0 + p * 16;
            const long long e = (long long)blockIdx.z * so
                              + (long long)(r0 + i) * cols + c0 + 2 * cp;
            *(uint32_t*)(oH + e) = pack2h(hi[i][2 * cp], hi[i][2 * cp + 1]);
            *(uint32_t*)(oL + e) = pack2h(lo[i][2 * cp], lo[i][2 * cp + 1]);
        }
    }
    if (oTH) {
#pragma unroll
        for (int p = 0; p < 2; ++p) {
            const int i = i0 + p * 16;
            const long long e = (long long)blockIdx.z * soT
                              + (long long)(c0 + i) * rows + r0 + 2 * cp;
            *(uint32_t*)(oTH + e) = pack2h(hi[2 * cp][i], hi[2 * cp + 1][i]);
        }
    }
}

// ===========================================================================
// Merged weight split: blockIdx.z selects 0:Wq, 1:Wk, 2:Wv(transposed).
// ===========================================================================
__global__ __launch_bounds__(256) void split_weights_kernel(
    const float* __restrict__ Wq, const float* __restrict__ Wk,
    const float* __restrict__ Wv,
    __half* __restrict__ Wqh, __half* __restrict__ Wql,
    __half* __restrict__ Wkh, __half* __restrict__ Wkl,
    __half* __restrict__ WvTh, __half* __restrict__ WvTl)
{
    __shared__ __half hi[32][34], lo[32][34];
    const int which = blockIdx.z;
    const float* I = which == 0 ? Wq : which == 1 ? Wk : Wv;
    const int c0 = blockIdx.x * 32;
    const int r0 = blockIdx.y * 32;
    const int tx = threadIdx.x & 31, ty = threadIdx.x >> 5;

#pragma unroll
    for (int i = ty; i < 32; i += 8) {
        const float v = I[(long long)(r0 + i) * DIMC + c0 + tx];
        f16_split(v, hi[i][tx], lo[i][tx]);
    }
    __syncthreads();

    const int i0 = threadIdx.x >> 4;
    const int cp = threadIdx.x & 15;
    if (which < 2) {
        __half* oH = which == 0 ? Wqh : Wkh;
        __half* oL = which == 0 ? Wql : Wkl;
#pragma unroll
        for (int p = 0; p < 2; ++p) {
            const int i = i0 + p * 16;
            const long long e = (long long)(r0 + i) * DIMC + c0 + 2 * cp;
            *(uint32_t*)(oH + e) = pack2h(hi[i][2 * cp], hi[i][2 * cp + 1]);
            *(uint32_t*)(oL + e) = pack2h(lo[i][2 * cp], lo[i][2 * cp + 1]);
        }
    } else {
#pragma unroll
        for (int p = 0; p < 2; ++p) {
            const int i = i0 + p * 16;
            const long long e = (long long)(c0 + i) * DIMC + r0 + 2 * cp;
            *(uint32_t*)(WvTh + e) = pack2h(hi[2 * cp][i], hi[2 * cp + 1][i]);
            *(uint32_t*)(WvTl + e) = pack2h(lo[2 * cp][i], lo[2 * cp + 1][i]);
        }
    }
}

// ===========================================================================
// Row softmax over S (fp32), writing fp16-split A = softmax(S).
// ===========================================================================
__global__ __launch_bounds__(256) void softmax_split_kernel(
    const float* __restrict__ S,
    __half* __restrict__ AH, __half* __restrict__ AL)
{
    __shared__ float red[8];
    const long long row = blockIdx.x;
    const float* p = S + row * DIMC;
    const int t = threadIdx.x;
    const int lane = t & 31, warp = t >> 5;

    const float v0 = p[2 * t];
    const float v1 = p[2 * t + 1];

    float m = fmaxf(v0, v1);
#pragma unroll
    for (int o = 16; o; o >>= 1) m = fmaxf(m, __shfl_xor_sync(0xFFFFFFFFu, m, o));
    if (lane == 0) red[warp] = m;
    __syncthreads();
    m = red[0];
#pragma unroll
    for (int w = 1; w < 8; ++w) m = fmaxf(m, red[w]);
    __syncthreads();

    const float e0 = expf(v0 - m);
    const float e1 = expf(v1 - m);
    float sum = e0 + e1;
#pragma unroll
    for (int o = 16; o; o >>= 1) sum += __shfl_xor_sync(0xFFFFFFFFu, sum, o);
    if (lane == 0) red[warp] = sum;
    __syncthreads();
    sum = red[0];
#pragma unroll
    for (int w = 1; w < 8; ++w) sum += red[w];
    const float inv = 1.0f / sum;

    __half h0, l0, h1, l1;
    f16_split(e0 * inv, h0, l0);
    f16_split(e1 * inv, h1, l1);
    *(uint32_t*)(AH + row * DIMC + 2 * t) = pack2h(h0, h1);
    *(uint32_t*)(AL + row * DIMC + 2 * t) = pack2h(l0, l1);
}

// ===========================================================================
// Launch chain (all GEMMs NT, fp16x2-split HMMA.16816, ldmatrix frags):
//   split x;  G = x.x^T (SYMMETRIC: 10/16 tiles + mirror, 3-term);
//   split weights; T = Wq.G (3-term); S = (1/tau) T.Wk^T (3-term);
//   A = softmax(S); M = A.Wv (3-term); out = M.x (2-TERM: x hi-only)
// ===========================================================================
extern "C" void kernel_launch(void* const* d_in, const int* in_sizes, int n_in,
                              void* d_out, int out_size)
{
    const float* x  = (const float*)d_in[0];
    const float* Wq = (const float*)d_in[1];
    const float* Wk = (const float*)d_in[2];
    const float* Wv = (const float*)d_in[3];
    float* out = (float*)d_out;

    __half *xh, *xl, *xTh, *Wqh, *Wql, *Wkh, *Wkl, *WvTh, *WvTl;
    __half *Gh, *Gl, *Th, *Tl, *Ahp, *Alp, *Mh, *Ml;
    float* S;
    cudaGetSymbolAddress((void**)&xh,   g_xh);
    cudaGetSymbolAddress((void**)&xl,   g_xl);
    cudaGetSymbolAddress((void**)&xTh,  g_xTh);
    cudaGetSymbolAddress((void**)&Wqh,  g_Wqh);
    cudaGetSymbolAddress((void**)&Wql,  g_Wql);
    cudaGetSymbolAddress((void**)&Wkh,  g_Wkh);
    cudaGetSymbolAddress((void**)&Wkl,  g_Wkl);
    cudaGetSymbolAddress((void**)&WvTh, g_WvTh);
    cudaGetSymbolAddress((void**)&WvTl, g_WvTl);
    cudaGetSymbolAddress((void**)&Gh,   g_Gh);
    cudaGetSymbolAddress((void**)&Gl,   g_Gl);
    cudaGetSymbolAddress((void**)&Th,   g_Th);
    cudaGetSymbolAddress((void**)&Tl,   g_Tl);
    cudaGetSymbolAddress((void**)&Ahp,  g_Ah);
    cudaGetSymbolAddress((void**)&Alp,  g_Al);
    cudaGetSymbolAddress((void**)&Mh,   g_Mh);
    cudaGetSymbolAddress((void**)&Ml,   g_Ml);
    cudaGetSymbolAddress((void**)&S,    g_S);

    cudaFuncSetAttribute(gemm_f16x2_nt,
                         cudaFuncAttributeMaxDynamicSharedMemorySize, SMEM_BYTES);

    const long long sX  = (long long)DIMC * NPTS;   // x / xT / out batch stride
    const long long sDD = (long long)DIMC * DIMC;
    const float inv_tau = (float)(1.0 / sqrt((double)DIMC));

    // split x (straight hi/lo + transposed hi)
    {
        dim3 gx(NPTS / 32, DIMC / 32, BATCH);
        split_f16_kernel<<<gx, 256>>>(x, xh, xl, xTh, DIMC, NPTS, sX, sX, sX);
    }

    // G[b] = x[b] . x[b]^T  -> split, SYMMETRIC: 10 upper-triangle tiles/batch
    {
        dim3 gG(10, 1, BATCH);
        gemm_f16x2_nt<<<gG, GTHREADS, SMEM_BYTES>>>(xh, xl, xh, xl,
            nullptr, Gh, Gl,
            NPTS, NPTS, NPTS, 0, DIMC, sX, sX, 0LL, sDD, 1.0f, 1);
    }

    // split weights
    {
        dim3 gw(DIMC / 32, DIMC / 32, 3);
        split_weights_kernel<<<gw, 256>>>(Wq, Wk, Wv,
            Wqh, Wql, Wkh, Wkl, WvTh, WvTl);
    }

    dim3 gSq(DIMC / BN, DIMC / BM, BATCH);   // 4 x 4 x 16
    dim3 gOut(NPTS / BN, DIMC / BM, BATCH);  // 32 x 4 x 16

    // T[b] = Wq . G[b]  (G symmetric) -> split
    gemm_f16x2_nt<<<gSq, GTHREADS, SMEM_BYTES>>>(Wqh, Wql, Gh, Gl,
        nullptr, Th, Tl,
        DIMC, DIMC, DIMC, 0, DIMC, 0LL, sDD, 0LL, sDD, 1.0f, 0);

    // S[b] = (1/tau) T[b] . Wk^T -> plain
    gemm_f16x2_nt<<<gSq, GTHREADS, SMEM_BYTES>>>(Th, Tl, Wkh, Wkl,
        S, nullptr, nullptr,
        DIMC, DIMC, DIMC, DIMC, 0, sDD, 0LL, sDD, 0LL, inv_tau, 0);

    // A = softmax(S) -> split
    softmax_split_kernel<<<BATCH * DIMC, 256>>>(S, Ahp, Alp);

    // M[b] = A[b] . Wv (B = WvT) -> split
    gemm_f16x2_nt<<<gSq, GTHREADS, SMEM_BYTES>>>(Ahp, Alp, WvTh, WvTl,
        nullptr, Mh, Ml,
        DIMC, DIMC, DIMC, 0, DIMC, sDD, 0LL, 0LL, sDD, 1.0f, 0);

    // out[b] = M[b] . x[b]  (B = xT, HI-ONLY -> 2-term) -> plain
    gemm_f16x2_nt<<<gOut, GTHREADS, SMEM_BYTES>>>(Mh, Ml, xTh, nullptr,
        out, nullptr, nullptr,
        DIMC, DIMC, DIMC, NPTS, 0, sDD, sX, sX, 0LL, 1.0f, 0);
}